// round 10
// baseline (speedup 1.0000x reference)
#include <cuda_runtime.h>
#include <cuda_fp16.h>
#include <cstdint>

#define N_GENES 20000
#define UNITS   10000
#define DEG     32
#define BATCH   128

// |feature| transposed to [gene][batch] in fp16: 5.12 MB, L2-resident.
// Row = 256B; each (unit, deg) gather reads one full row, coalesced.
// 82 MB of gather traffic vs ~6300 B/cyc achievable LTS cap: the gather
// kernel sits near the memory-system floor (invariant across R4-R9).
__device__ __half g_featT[(size_t)N_GENES * BATCH];

// ---------------------------------------------------------------------------
// K1: tiled transpose + fabs + fp16.  feature [128, 20000] -> featT [N, B]
// Triggers programmatic launch completion so the gather kernel's preamble
// overlaps with this kernel's tail.
// ---------------------------------------------------------------------------
__global__ void transpose_abs_kernel(const float* __restrict__ feature) {
    __shared__ float tile[32][33];               // tile[batch][gene]
    const int gx = blockIdx.x * 32;
    const int bx = blockIdx.y * 32;
    const int tx = threadIdx.x, ty = threadIdx.y;

#pragma unroll
    for (int k = 0; k < 32; k += 8)
        tile[ty + k][tx] = fabsf(feature[(size_t)(bx + ty + k) * N_GENES + (gx + tx)]);
    __syncthreads();

    const int t = ty * 32 + tx;
#pragma unroll
    for (int iter = 0; iter < 2; iter++) {
        const int tt  = iter * 256 + t;
        const int g_l = tt >> 4;                 // 0..31
        const int p   = tt & 15;                 // batch pair
        const __half2 h = __floats2half2_rn(tile[2 * p][g_l], tile[2 * p + 1][g_l]);
        *(__half2*)&g_featT[(size_t)(gx + g_l) * BATCH + bx + 2 * p] = h;
    }
#if __CUDA_ARCH__ >= 900
    cudaTriggerProgrammaticLaunchCompletion();
#endif
}

// ---------------------------------------------------------------------------
// K2: gather-sum (R5 best config). One warp per unit; each LDG.128 covers two
// gene rows (half-warp per gene, 16B batch slice per lane); 4 loads batched
// in flight. PDL: ppi/kern/bias preamble runs before the grid-dependency
// sync, overlapping the transpose. half2 accumulate, fp32 flush every 8
// genes; cross-half shfl_xor(16); smem-staged coalesced streaming output.
// ---------------------------------------------------------------------------
__global__ void __launch_bounds__(256, 5) ppi_gather_kernel(
    const int*   __restrict__ ppi,     // int32 (JAX x64-disabled)
    const float* __restrict__ kern,
    const float* __restrict__ bias,
    float*       __restrict__ out)
{
    __shared__ float tile[8][BATCH + 4];

    const int lane   = threadIdx.x & 31;
    const int hlane  = lane & 15;                 // batch-slice owner (16B)
    const int hsel   = lane >> 4;                 // 0: even gene, 1: odd gene
    const int warp   = threadIdx.x >> 5;
    const int u_base = blockIdx.x * 8;
    const int u      = u_base + warp;

    // ---- preamble: independent of featT, runs during transpose ----
    const int myoff = ppi[(size_t)u * DEG + lane] << 8;   // row byte-offset
    const float kv  = kern[u];
    const float bv  = bias[u];
    const char* base = (const char*)g_featT + hlane * 16;

#if __CUDA_ARCH__ >= 900
    cudaGridDependencySynchronize();              // featT ready beyond here
#endif

    float facc[8];
#pragma unroll
    for (int j = 0; j < 8; j++) facc[j] = 0.f;

#pragma unroll
    for (int half = 0; half < 2; half++) {        // 2 flush periods x 16 genes
        __half2 hacc[4];
#pragma unroll
        for (int j = 0; j < 4; j++) hacc[j] = __floats2half2_rn(0.f, 0.f);

#pragma unroll
        for (int bb = 0; bb < 2; bb++) {          // 2 batches of 4 LDG.128
            uint4 raw[4];
#pragma unroll
            for (int q = 0; q < 4; q++) {
                const int it  = half * 8 + bb * 4 + q;          // 0..15
                const int off = __shfl_sync(0xffffffffu, myoff, 2 * it + hsel);
                raw[q] = *(const uint4*)(base + off);
            }
#pragma unroll
            for (int q = 0; q < 4; q++) {
                hacc[0] = __hadd2(hacc[0], *(const __half2*)&raw[q].x);
                hacc[1] = __hadd2(hacc[1], *(const __half2*)&raw[q].y);
                hacc[2] = __hadd2(hacc[2], *(const __half2*)&raw[q].z);
                hacc[3] = __hadd2(hacc[3], *(const __half2*)&raw[q].w);
            }
        }
#pragma unroll
        for (int j = 0; j < 4; j++) {             // fp32 flush
            const float2 f = __half22float2(hacc[j]);
            facc[2 * j]     += f.x;
            facc[2 * j + 1] += f.y;
        }
    }

    // Combine the two half-warps (same batch slice, disjoint gene subsets).
#pragma unroll
    for (int j = 0; j < 8; j++)
        facc[j] += __shfl_xor_sync(0xffffffffu, facc[j], 16);

    if (lane < 16) {                              // conflict-free 512B row
        float r[8];
#pragma unroll
        for (int j = 0; j < 8; j++)
            r[j] = tanhf(fmaf(facc[j], kv, bv));
        *(float4*)&tile[warp][hlane * 8]     = make_float4(r[0], r[1], r[2], r[3]);
        *(float4*)&tile[warp][hlane * 8 + 4] = make_float4(r[4], r[5], r[6], r[7]);
    }
    __syncthreads();

    // Coalesced streaming output: 8-thread groups, contiguous 32B chunks.
    for (int t = threadIdx.x; t < BATCH * 8; t += 256) {
        const int u_l = t & 7;
        const int b   = t >> 3;
        __stcs(&out[(size_t)b * UNITS + (u_base + u_l)], tile[u_l][b]);
    }
}

// ---------------------------------------------------------------------------
extern "C" void kernel_launch(void* const* d_in, const int* in_sizes, int n_in,
                              void* d_out, int out_size) {
    const float* feature = (const float*)d_in[0];
    const int*   ppi     = (const int*)d_in[1];
    const float* kern    = (const float*)d_in[2];
    const float* bias    = (const float*)d_in[3];
    float*       out     = (float*)d_out;

    dim3 tgrid(N_GENES / 32, BATCH / 32);   // (625, 4)
    dim3 tblock(32, 8);
    transpose_abs_kernel<<<tgrid, tblock>>>(feature);

    // Gather with programmatic dependent launch: preamble overlaps transpose.
    cudaLaunchConfig_t cfg = {};
    cfg.gridDim  = dim3(UNITS / 8, 1, 1);   // 1250 CTAs
    cfg.blockDim = dim3(256, 1, 1);
    cfg.dynamicSmemBytes = 0;
    cfg.stream = (cudaStream_t)0;           // legacy stream = capture stream
    cudaLaunchAttribute attr[1];
    attr[0].id = cudaLaunchAttributeProgrammaticStreamSerialization;
    attr[0].val.programmaticStreamSerializationAllowed = 1;
    cfg.attrs = attr;
    cfg.numAttrs = 1;
    cudaLaunchKernelEx(&cfg, ppi_gather_kernel, ppi, kern, bias, out);
}